// round 1
// baseline (speedup 1.0000x reference)
#include <cuda_runtime.h>
#include <cstdint>
#include <cstddef>

// Problem: out[b] = weight[b] + top1000_scatter_mask(|difference[b]|), B=64, N=1M/batch.
// Strategy: one fused streaming pass (copy weight->out + gather |x|>=2.5 candidates),
// then exact per-batch radix-select + scatter over ~12K candidates.

namespace {

constexpr int B       = 64;
constexpr int NPB     = 1 << 20;      // elements per batch (1024*1024, C=1)
constexpr int TOPN    = 1000;
constexpr int CAP     = 131072;       // candidate capacity per batch (~10x expected)
constexpr unsigned CUT = 0x40200000u; // float bits of 2.5f (abs-key cutoff)

// Static scratch (allocation-free): 64 MB candidate buffers + counters.
__device__ unsigned g_cnt[B];
__device__ unsigned g_key[B][CAP];
__device__ unsigned g_idx[B][CAP];

__global__ void k_zero() {
    if (threadIdx.x < B) g_cnt[threadIdx.x] = 0;
}

// Fused pass: out = weight (streaming), gather candidates with |diff| >= 2.5.
// One thread = one float4 (4 elements). Warp never straddles a batch boundary
// (262144 float4s per batch, divisible by 32).
__global__ void __launch_bounds__(256) k_main(const float4* __restrict__ diff,
                                              const float4* __restrict__ w,
                                              float4* __restrict__ out) {
    unsigned t = blockIdx.x * 256u + threadIdx.x;     // float4 index, 0..16M-1
    float4 d = __ldcs(&diff[t]);
    __stcs(&out[t], __ldcs(&w[t]));

    unsigned b      = t >> 18;                 // batch = t / 262144
    unsigned e0     = (t & 0x3FFFFu) << 2;     // element index within batch
    unsigned lane   = threadIdx.x & 31u;
    unsigned ltmask = (1u << lane) - 1u;

    unsigned keys[4] = {__float_as_uint(d.x) & 0x7FFFFFFFu,
                        __float_as_uint(d.y) & 0x7FFFFFFFu,
                        __float_as_uint(d.z) & 0x7FFFFFFFu,
                        __float_as_uint(d.w) & 0x7FFFFFFFu};
#pragma unroll
    for (int j = 0; j < 4; ++j) {
        bool sel = keys[j] >= CUT;
        unsigned bal = __ballot_sync(0xFFFFFFFFu, sel);
        if (bal) {
            int leader = __ffs(bal) - 1;
            unsigned pos = 0;
            if ((int)lane == leader) pos = atomicAdd(&g_cnt[b], (unsigned)__popc(bal));
            pos = __shfl_sync(0xFFFFFFFFu, pos, leader);
            if (sel) {
                unsigned slot = pos + (unsigned)__popc(bal & ltmask);
                if (slot < CAP) {
                    g_key[b][slot] = keys[j];
                    g_idx[b][slot] = e0 + j;
                }
            }
        }
    }
}

// Per-batch exact selection + scatter. One block per batch.
// Fast path: radix-select over candidates (count M in [TOPN, CAP] guarantees
// completeness: the 1000th-largest key is >= CUT, so all winners were gathered).
// Fallback path (never triggers on the bench inputs): same radix logic over the
// full 1M elements read from global memory.
__global__ void __launch_bounds__(256) k_select(const float* __restrict__ diff,
                                                float* __restrict__ out,
                                                const int* __restrict__ ep) {
    int epoch = ep[0];
    if (!((epoch > 1000) && (epoch < 18000) && (epoch % 200 == 0))) return;

    int b = blockIdx.x;
    unsigned M    = g_cnt[b];
    bool     fast = (M >= (unsigned)TOPN) && (M <= (unsigned)CAP);
    unsigned cnt  = fast ? M : (unsigned)NPB;
    size_t   gbase = (size_t)b * (size_t)NPB;

    __shared__ unsigned hist[256];
    __shared__ unsigned s_prefix, s_rem;
    if (threadIdx.x == 0) { s_prefix = 0u; s_rem = (unsigned)TOPN; }
    __syncthreads();

    const int      SH[4] = {23, 15, 7, 0};
    const unsigned BM[4] = {255u, 255u, 255u, 127u};

#pragma unroll 1
    for (int r = 0; r < 4; ++r) {
        hist[threadIdx.x & 255u] = 0u;   // blockDim == 256
        __syncthreads();
        int      sh     = SH[r];
        int      hish   = sh + (r == 3 ? 7 : 8);  // bits already resolved start here
        unsigned prefix = s_prefix;
        for (unsigned i = threadIdx.x; i < cnt; i += 256u) {
            unsigned key = fast ? g_key[b][i]
                                : (__float_as_uint(diff[gbase + i]) & 0x7FFFFFFFu);
            if (((key ^ prefix) >> hish) == 0u)
                atomicAdd(&hist[(key >> sh) & BM[r]], 1u);
        }
        __syncthreads();
        if (threadIdx.x == 0) {
            unsigned need = s_rem, acc = 0u;
            int bin = (int)BM[r];
            for (; bin > 0; --bin) {
                unsigned c = hist[bin];
                if (acc + c >= need) break;
                acc += c;
            }
            s_rem    = need - acc;
            s_prefix = prefix | ((unsigned)bin << sh);
        }
        __syncthreads();
    }

    unsigned thr = s_prefix;   // exact 31-bit threshold key (rank-1000)
    unsigned req = s_rem;      // how many equal-to-threshold elements to include

    for (unsigned i = threadIdx.x; i < cnt; i += 256u) {
        unsigned key, idx;
        if (fast) { key = g_key[b][i]; idx = g_idx[b][i]; }
        else      { key = __float_as_uint(diff[gbase + i]) & 0x7FFFFFFFu; idx = i; }
        if (key > thr) {
            out[gbase + idx] += 1.0f;
        } else if (key == thr) {
            // Tie-break exactly like jax top_k: smallest original indices win.
            unsigned rank = 0u;
            for (unsigned j = 0; j < cnt; ++j) {
                unsigned kj = fast ? g_key[b][j]
                                   : (__float_as_uint(diff[gbase + j]) & 0x7FFFFFFFu);
                if (kj == thr) {
                    unsigned ij = fast ? g_idx[b][j] : j;
                    if (ij < idx) ++rank;
                }
            }
            if (rank < req) out[gbase + idx] += 1.0f;
        }
    }
}

} // namespace

extern "C" void kernel_launch(void* const* d_in, const int* in_sizes, int n_in,
                              void* d_out, int out_size) {
    // metadata order: difference (f32, 64M), weight (f32, 64M), epoch, iteration
    const float* diff = (const float*)d_in[0];
    const float* w    = (const float*)d_in[1];
    const int*   ep   = (const int*)d_in[2];
    float*       out  = (float*)d_out;

    k_zero<<<1, 64>>>();
    k_main<<<(B * (NPB / 4)) / 256, 256>>>((const float4*)diff, (const float4*)w,
                                           (float4*)out);
    k_select<<<B, 256>>>(diff, out, ep);
}

// round 2
// speedup vs baseline: 1.3255x; 1.3255x over previous
#include <cuda_runtime.h>
#include <cstdint>
#include <cstddef>

// Problem: out[b] = weight[b] + top1000_scatter_mask(|difference[b]|), B=64, N=1M/batch.
// R2: fused streaming pass with BLOCK-AGGREGATED candidate gather (1 padded global
// atomic per block) to kill the L2 same-line atomic serialization seen in R1.

namespace {

constexpr int B       = 64;
constexpr int NPB     = 1 << 20;      // elements per batch
constexpr int TOPN    = 1000;
constexpr int CAP     = 131072;       // candidate capacity per batch (~10x expected)
constexpr unsigned CUT = 0x40200000u; // float bits of 2.5f (abs-key cutoff)
constexpr int CNT_STRIDE = 32;        // 128B between counters -> distinct L2 lines

// Static scratch (allocation-free).
__device__ unsigned g_cnt[B * CNT_STRIDE];
__device__ unsigned g_key[B][CAP];
__device__ unsigned g_idx[B][CAP];

__global__ void k_zero() {
    if (threadIdx.x < B) g_cnt[threadIdx.x * CNT_STRIDE] = 0;
}

// Fused pass: out = weight (streaming), gather candidates with |diff| >= 2.5.
// Block = 256 threads x 1 float4 = 1024 elements, always within one batch
// (262144 float4s per batch, divisible by 256).
__global__ void __launch_bounds__(256) k_main(const float4* __restrict__ diff,
                                              const float4* __restrict__ w,
                                              float4* __restrict__ out) {
    __shared__ unsigned s_key[1024];
    __shared__ unsigned s_idx[1024];
    __shared__ unsigned s_n, s_base;
    if (threadIdx.x == 0) s_n = 0u;
    __syncthreads();

    unsigned t = blockIdx.x * 256u + threadIdx.x;     // float4 index
    float4 d = __ldcs(&diff[t]);
    __stcs(&out[t], __ldcs(&w[t]));

    unsigned b  = blockIdx.x >> 10;                   // batch (uniform per block)
    unsigned e0 = (t & 0x3FFFFu) << 2;                // element index within batch

    unsigned keys[4] = {__float_as_uint(d.x) & 0x7FFFFFFFu,
                        __float_as_uint(d.y) & 0x7FFFFFFFu,
                        __float_as_uint(d.z) & 0x7FFFFFFFu,
                        __float_as_uint(d.w) & 0x7FFFFFFFu};
#pragma unroll
    for (int j = 0; j < 4; ++j) {
        if (keys[j] >= CUT) {               // ~1.2% of elements
            unsigned p = atomicAdd(&s_n, 1u);
            s_key[p] = keys[j];
            s_idx[p] = e0 + j;
        }
    }
    __syncthreads();

    unsigned n = s_n;
    if (n) {
        if (threadIdx.x == 0)
            s_base = atomicAdd(&g_cnt[b * CNT_STRIDE], n);
        __syncthreads();
        unsigned base = s_base;
        for (unsigned i = threadIdx.x; i < n; i += 256u) {
            unsigned slot = base + i;
            if (slot < (unsigned)CAP) {
                g_key[b][slot] = s_key[i];
                g_idx[b][slot] = s_idx[i];
            }
        }
    }
}

// Per-batch exact selection + scatter. One block per batch.
// Fast path: radix-select over gathered candidates (complete whenever the
// rank-1000 key >= CUT, guaranteed if M in [TOPN, CAP]). Fallback: same radix
// logic over the full 1M elements from global memory (never triggers here).
__global__ void __launch_bounds__(256) k_select(const float* __restrict__ diff,
                                                float* __restrict__ out,
                                                const int* __restrict__ ep) {
    int epoch = ep[0];
    if (!((epoch > 1000) && (epoch < 18000) && (epoch % 200 == 0))) return;

    int b = blockIdx.x;
    unsigned M    = g_cnt[b * CNT_STRIDE];
    bool     fast = (M >= (unsigned)TOPN) && (M <= (unsigned)CAP);
    unsigned cnt  = fast ? M : (unsigned)NPB;
    size_t   gbase = (size_t)b * (size_t)NPB;

    __shared__ unsigned hist[256];
    __shared__ unsigned s_prefix, s_rem;
    if (threadIdx.x == 0) { s_prefix = 0u; s_rem = (unsigned)TOPN; }
    __syncthreads();

    const int      SH[4] = {23, 15, 7, 0};
    const unsigned BM[4] = {255u, 255u, 255u, 127u};

#pragma unroll 1
    for (int r = 0; r < 4; ++r) {
        hist[threadIdx.x & 255u] = 0u;
        __syncthreads();
        int      sh     = SH[r];
        int      hish   = sh + (r == 3 ? 7 : 8);
        unsigned prefix = s_prefix;
        for (unsigned i = threadIdx.x; i < cnt; i += 256u) {
            unsigned key = fast ? g_key[b][i]
                                : (__float_as_uint(diff[gbase + i]) & 0x7FFFFFFFu);
            if (((key ^ prefix) >> hish) == 0u)
                atomicAdd(&hist[(key >> sh) & BM[r]], 1u);
        }
        __syncthreads();
        if (threadIdx.x == 0) {
            unsigned need = s_rem, acc = 0u;
            int bin = (int)BM[r];
            for (; bin > 0; --bin) {
                unsigned c = hist[bin];
                if (acc + c >= need) break;
                acc += c;
            }
            s_rem    = need - acc;
            s_prefix = prefix | ((unsigned)bin << sh);
        }
        __syncthreads();
    }

    unsigned thr = s_prefix;   // exact 31-bit threshold key (rank-1000)
    unsigned req = s_rem;      // how many == threshold to include

    for (unsigned i = threadIdx.x; i < cnt; i += 256u) {
        unsigned key, idx;
        if (fast) { key = g_key[b][i]; idx = g_idx[b][i]; }
        else      { key = __float_as_uint(diff[gbase + i]) & 0x7FFFFFFFu; idx = i; }
        if (key > thr) {
            out[gbase + idx] += 1.0f;
        } else if (key == thr) {
            // Tie-break exactly like jax top_k: smallest original indices win.
            unsigned rank = 0u;
            for (unsigned j = 0; j < cnt; ++j) {
                unsigned kj = fast ? g_key[b][j]
                                   : (__float_as_uint(diff[gbase + j]) & 0x7FFFFFFFu);
                if (kj == thr) {
                    unsigned ij = fast ? g_idx[b][j] : j;
                    if (ij < idx) ++rank;
                }
            }
            if (rank < req) out[gbase + idx] += 1.0f;
        }
    }
}

} // namespace

extern "C" void kernel_launch(void* const* d_in, const int* in_sizes, int n_in,
                              void* d_out, int out_size) {
    const float* diff = (const float*)d_in[0];
    const float* w    = (const float*)d_in[1];
    const int*   ep   = (const int*)d_in[2];
    float*       out  = (float*)d_out;

    k_zero<<<1, 64>>>();
    k_main<<<(B * (NPB / 4)) / 256, 256>>>((const float4*)diff, (const float4*)w,
                                           (float4*)out);
    k_select<<<B, 256>>>(diff, out, ep);
}

// round 3
// speedup vs baseline: 3.1720x; 2.3931x over previous
#include <cuda_runtime.h>
#include <cstdint>
#include <cstddef>

// out[b] = weight[b] + top1000_scatter_mask(|difference[b]|), B=64, N=1M/batch.
// R3: atomic-free candidate gather with deterministic per-block slot regions.
// (R2 post-mortem: per-wave same-address global atomics serialized ~27cyc/op.)

namespace {

constexpr int B      = 64;
constexpr int NPB    = 1 << 20;       // elements per batch
constexpr int TOPN   = 1000;
constexpr unsigned CUT = 0x40200000u; // float bits of 2.5f
constexpr int BPB    = 1024;          // 1024-elem blocks per batch
constexpr int SLOTS  = 64;            // fixed slots per block (mean fill ~12.7)
constexpr int NSLOT  = BPB * SLOTS;   // 65536 slots per batch
constexpr int OCAP   = 8192;          // overflow capacity per batch (never used in practice)
constexpr int MAXTIES = 256;

__device__ unsigned g_key[B][NSLOT];
__device__ unsigned g_idx[B][NSLOT];
__device__ unsigned g_bcnt[B * BPB];     // overwritten every replay, no reset needed
__device__ unsigned g_okey[B][OCAP];
__device__ unsigned g_oidx[B][OCAP];
__device__ unsigned g_ocnt[B * 32];      // padded; reset by k_select each replay

// Streaming pass: out = weight; gather |diff| >= 2.5 into fixed per-block slots.
__global__ void __launch_bounds__(256) k_main(const float4* __restrict__ diff,
                                              const float4* __restrict__ w,
                                              float4* __restrict__ out) {
    __shared__ unsigned s_n;
    if (threadIdx.x == 0) s_n = 0u;
    __syncthreads();

    unsigned t   = blockIdx.x * 256u + threadIdx.x;   // float4 index
    float4 d = __ldcs(&diff[t]);
    __stcs(&out[t], __ldcs(&w[t]));

    unsigned b    = blockIdx.x >> 10;
    unsigned base = (blockIdx.x & 1023u) * (unsigned)SLOTS;
    unsigned e0   = (t & 0x3FFFFu) << 2;

    unsigned keys[4] = {__float_as_uint(d.x) & 0x7FFFFFFFu,
                        __float_as_uint(d.y) & 0x7FFFFFFFu,
                        __float_as_uint(d.z) & 0x7FFFFFFFu,
                        __float_as_uint(d.w) & 0x7FFFFFFFu};
#pragma unroll
    for (int j = 0; j < 4; ++j) {
        if (keys[j] >= CUT) {                  // ~1.24% of elements
            unsigned p = atomicAdd(&s_n, 1u);  // shared: cheap, ~13/block
            if (p < (unsigned)SLOTS) {
                g_key[b][base + p] = keys[j];
                g_idx[b][base + p] = e0 + j;
            } else {                           // probability ~1e-20: spill path
                unsigned o = atomicAdd(&g_ocnt[b * 32], 1u);
                if (o < (unsigned)OCAP) {
                    g_okey[b][o] = keys[j];
                    g_oidx[b][o] = e0 + j;
                }
            }
        }
    }
    __syncthreads();
    if (threadIdx.x == 0)
        g_bcnt[blockIdx.x] = (s_n < (unsigned)SLOTS) ? s_n : (unsigned)SLOTS;
}

// Per-batch exact radix-select + scatter. One block per batch.
__global__ void __launch_bounds__(256) k_select(const float* __restrict__ diff,
                                                float* __restrict__ out,
                                                const int* __restrict__ ep) {
    int b = blockIdx.x;
    int epoch = ep[0];
    bool hot = (epoch > 1000) && (epoch < 18000) && (epoch % 200 == 0);
    if (!hot) { if (threadIdx.x == 0) g_ocnt[b * 32] = 0; return; }

    __shared__ unsigned s_bcnt[BPB];
    __shared__ unsigned hist[256];
    __shared__ unsigned s_prefix, s_rem, s_tot, s_tcnt;
    __shared__ unsigned s_tidx[MAXTIES];

    unsigned ovraw = g_ocnt[b * 32];
    unsigned ovf   = (ovraw > (unsigned)OCAP) ? (unsigned)OCAP : ovraw;

    if (threadIdx.x == 0) { s_prefix = 0u; s_rem = (unsigned)TOPN; s_tot = 0u; s_tcnt = 0u; }
    __syncthreads();

    unsigned tl = 0;
    for (unsigned i = threadIdx.x; i < (unsigned)BPB; i += 256u) {
        unsigned c = g_bcnt[b * BPB + i];
        s_bcnt[i] = c;
        tl += c;
    }
    for (int o = 16; o; o >>= 1) tl += __shfl_down_sync(0xFFFFFFFFu, tl, o);
    if ((threadIdx.x & 31u) == 0u) atomicAdd(&s_tot, tl);
    __syncthreads();

    unsigned total = s_tot + ovf;
    // Fast path valid iff all >=CUT elements were captured AND they cover top-1000.
    bool fast = (total >= (unsigned)TOPN) && (ovraw <= (unsigned)OCAP);
    size_t gbase = (size_t)b * (size_t)NPB;
    unsigned dom = fast ? (unsigned)NSLOT + ovf : (unsigned)NPB;

    auto fetch = [&](unsigned i, unsigned& key, unsigned& idx) -> bool {
        if (!fast) {
            key = __float_as_uint(diff[gbase + i]) & 0x7FFFFFFFu; idx = i; return true;
        }
        if (i < (unsigned)NSLOT) {
            if ((i & (unsigned)(SLOTS - 1)) >= s_bcnt[i >> 6]) return false;
            key = g_key[b][i]; idx = g_idx[b][i]; return true;
        }
        unsigned o = i - (unsigned)NSLOT;
        key = g_okey[b][o]; idx = g_oidx[b][o]; return true;
    };

    // 4-round radix select over 31-bit abs keys (msb->lsb: 8,8,8,7 bits).
    const int      SH[4] = {23, 15, 7, 0};
    const unsigned BM[4] = {255u, 255u, 255u, 127u};
#pragma unroll 1
    for (int r = 0; r < 4; ++r) {
        hist[threadIdx.x & 255u] = 0u;
        __syncthreads();
        int      sh     = SH[r];
        int      hish   = sh + (r == 3 ? 7 : 8);
        unsigned prefix = s_prefix;
        for (unsigned i = threadIdx.x; i < dom; i += 256u) {
            unsigned key, idx;
            if (!fetch(i, key, idx)) continue;
            if (((key ^ prefix) >> hish) == 0u)
                atomicAdd(&hist[(key >> sh) & BM[r]], 1u);
        }
        __syncthreads();
        if (threadIdx.x == 0) {
            unsigned need = s_rem, acc = 0u;
            int bin = (int)BM[r];
            for (; bin > 0; --bin) {
                unsigned c = hist[bin];
                if (acc + c >= need) break;
                acc += c;
            }
            s_rem    = need - acc;
            s_prefix = prefix | ((unsigned)bin << sh);
        }
        __syncthreads();
    }

    unsigned thr = s_prefix;   // exact rank-1000 key
    unsigned req = s_rem;      // how many == thr to include

    // Scatter strict winners; collect ties.
    for (unsigned i = threadIdx.x; i < dom; i += 256u) {
        unsigned key, idx;
        if (!fetch(i, key, idx)) continue;
        if (key > thr) {
            out[gbase + idx] += 1.0f;
        } else if (key == thr) {
            unsigned p = atomicAdd(&s_tcnt, 1u);
            if (p < (unsigned)MAXTIES) s_tidx[p] = idx;
        }
    }
    __syncthreads();

    unsigned tc = s_tcnt;
    if (tc <= (unsigned)MAXTIES) {
        // Parallel tie-break: smallest original indices win (jax top_k order).
        for (unsigned t = threadIdx.x; t < tc; t += 256u) {
            unsigned my = s_tidx[t], rank = 0u;
            for (unsigned j = 0; j < tc; ++j) rank += (s_tidx[j] < my) ? 1u : 0u;
            if (rank < req) out[gbase + my] += 1.0f;
        }
    } else {
        // Degenerate many-ties fallback (exact, slow; unreachable on bench data).
        for (unsigned i = threadIdx.x; i < dom; i += 256u) {
            unsigned key, idx;
            if (!fetch(i, key, idx)) continue;
            if (key != thr) continue;
            unsigned rank = 0u;
            for (unsigned j = 0; j < dom; ++j) {
                unsigned kj, ij;
                if (!fetch(j, kj, ij)) continue;
                if (kj == thr && ij < idx) ++rank;
            }
            if (rank < req) out[gbase + idx] += 1.0f;
        }
    }
    __syncthreads();
    if (threadIdx.x == 0) g_ocnt[b * 32] = 0;   // reset for next replay
}

} // namespace

extern "C" void kernel_launch(void* const* d_in, const int* in_sizes, int n_in,
                              void* d_out, int out_size) {
    const float* diff = (const float*)d_in[0];
    const float* w    = (const float*)d_in[1];
    const int*   ep   = (const int*)d_in[2];
    float*       out  = (float*)d_out;

    k_main<<<B * BPB, 256>>>((const float4*)diff, (const float4*)w, (float4*)out);
    k_select<<<B, 256>>>(diff, out, ep);
}

// round 4
// speedup vs baseline: 9.1598x; 2.8877x over previous
#include <cuda_runtime.h>
#include <cstdint>
#include <cstddef>

// out[b] = weight[b] + top1000_scatter_mask(|difference[b]|), B=64, N=1M/batch.
// R4: add k_compact (sparse 65536 slots -> dense ~13K candidates, 1024 blocks)
// so k_select's 5 scan passes run over a 5x smaller, branch-free, dense domain.

namespace {

constexpr int B      = 64;
constexpr int NPB    = 1 << 20;
constexpr int TOPN   = 1000;
constexpr unsigned CUT = 0x40200000u; // 2.5f abs-key cutoff
constexpr int BPB    = 1024;          // 1024-elem blocks per batch in k_main
constexpr int SLOTS  = 64;            // slots per k_main block (mean fill ~12.7)
constexpr int NSLOT  = BPB * SLOTS;   // 65536 sparse slots per batch
constexpr int CHUNKS = 16;            // k_compact blocks per batch
constexpr int CSLOT  = NSLOT / CHUNKS;// 4096 slots per compact block
constexpr int OCAP   = 8192;
constexpr int MAXTIES = 256;

__device__ unsigned g_key[B][NSLOT];
__device__ unsigned g_idx[B][NSLOT];
__device__ unsigned g_bcnt[B * BPB];      // overwritten every replay
__device__ unsigned g_dkey[B][NSLOT];     // dense candidates
__device__ unsigned g_didx[B][NSLOT];
__device__ unsigned g_dcnt[B * 32];       // padded; reset by k_select
__device__ unsigned g_okey[B][OCAP];
__device__ unsigned g_oidx[B][OCAP];
__device__ unsigned g_ocnt[B * 32];       // padded; reset by k_select

// Streaming pass: out = weight; gather |diff| >= 2.5 into fixed per-block slots.
__global__ void __launch_bounds__(256) k_main(const float4* __restrict__ diff,
                                              const float4* __restrict__ w,
                                              float4* __restrict__ out) {
    __shared__ unsigned s_n;
    if (threadIdx.x == 0) s_n = 0u;
    __syncthreads();

    unsigned t = blockIdx.x * 256u + threadIdx.x;
    float4 d = __ldcs(&diff[t]);
    __stcs(&out[t], __ldcs(&w[t]));

    unsigned b    = blockIdx.x >> 10;
    unsigned base = (blockIdx.x & 1023u) * (unsigned)SLOTS;
    unsigned e0   = (t & 0x3FFFFu) << 2;

    unsigned keys[4] = {__float_as_uint(d.x) & 0x7FFFFFFFu,
                        __float_as_uint(d.y) & 0x7FFFFFFFu,
                        __float_as_uint(d.z) & 0x7FFFFFFFu,
                        __float_as_uint(d.w) & 0x7FFFFFFFu};
#pragma unroll
    for (int j = 0; j < 4; ++j) {
        if (keys[j] >= CUT) {                  // ~1.24%
            unsigned p = atomicAdd(&s_n, 1u);
            if (p < (unsigned)SLOTS) {
                g_key[b][base + p] = keys[j];
                g_idx[b][base + p] = e0 + j;
            } else {                           // ~1e-20 probability spill
                unsigned o = atomicAdd(&g_ocnt[b * 32], 1u);
                if (o < (unsigned)OCAP) {
                    g_okey[b][o] = keys[j];
                    g_oidx[b][o] = e0 + j;
                }
            }
        }
    }
    __syncthreads();
    if (threadIdx.x == 0)
        g_bcnt[blockIdx.x] = (s_n < (unsigned)SLOTS) ? s_n : (unsigned)SLOTS;
}

// Compact sparse slots into dense per-batch arrays. grid = B*CHUNKS.
__global__ void __launch_bounds__(256) k_compact() {
    __shared__ unsigned s_key[CSLOT];
    __shared__ unsigned s_idx[CSLOT];
    __shared__ unsigned s_n, s_base;
    if (threadIdx.x == 0) s_n = 0u;
    __syncthreads();

    unsigned b     = blockIdx.x / (unsigned)CHUNKS;
    unsigned chunk = blockIdx.x % (unsigned)CHUNKS;
    unsigned sbase = chunk * (unsigned)CSLOT;          // slot offset in batch
    unsigned rbase = b * (unsigned)BPB + chunk * (unsigned)(CSLOT / SLOTS);

    for (unsigned i = threadIdx.x; i < (unsigned)CSLOT; i += 256u) {
        unsigned cnt = g_bcnt[rbase + (i >> 6)];
        if ((i & 63u) < cnt) {
            unsigned p = atomicAdd(&s_n, 1u);
            s_key[p] = g_key[b][sbase + i];
            s_idx[p] = g_idx[b][sbase + i];
        }
    }
    __syncthreads();
    unsigned n = s_n;
    if (n) {
        if (threadIdx.x == 0) s_base = atomicAdd(&g_dcnt[b * 32], n);
        __syncthreads();
        unsigned base = s_base;
        for (unsigned i = threadIdx.x; i < n; i += 256u) {
            g_dkey[b][base + i] = s_key[i];
            g_didx[b][base + i] = s_idx[i];
        }
    }
}

// Per-batch exact radix-select + scatter over the dense domain. One block/batch.
__global__ void __launch_bounds__(512) k_select(const float* __restrict__ diff,
                                                float* __restrict__ out,
                                                const int* __restrict__ ep) {
    int b = blockIdx.x;
    int epoch = ep[0];
    bool hot = (epoch > 1000) && (epoch < 18000) && (epoch % 200 == 0);
    if (!hot) {
        if (threadIdx.x == 0) { g_ocnt[b * 32] = 0; g_dcnt[b * 32] = 0; }
        return;
    }

    __shared__ unsigned hist[256];
    __shared__ unsigned s_prefix, s_rem, s_tcnt;
    __shared__ unsigned s_tidx[MAXTIES];

    unsigned dcnt  = g_dcnt[b * 32];
    if (dcnt > (unsigned)NSLOT) dcnt = (unsigned)NSLOT;
    unsigned ovraw = g_ocnt[b * 32];
    unsigned ovf   = (ovraw > (unsigned)OCAP) ? (unsigned)OCAP : ovraw;
    unsigned total = dcnt + ovf;
    bool fast = (total >= (unsigned)TOPN) && (ovraw <= (unsigned)OCAP);
    size_t gbase = (size_t)b * (size_t)NPB;
    unsigned dom = fast ? total : (unsigned)NPB;

    if (threadIdx.x == 0) { s_prefix = 0u; s_rem = (unsigned)TOPN; s_tcnt = 0u; }
    __syncthreads();

    auto fetch = [&](unsigned i, unsigned& key, unsigned& idx) {
        if (!fast) {
            key = __float_as_uint(diff[gbase + i]) & 0x7FFFFFFFu; idx = i;
        } else if (i < dcnt) {
            key = g_dkey[b][i]; idx = g_didx[b][i];
        } else {
            key = g_okey[b][i - dcnt]; idx = g_oidx[b][i - dcnt];
        }
    };

    // 4-round radix select over 31-bit abs keys (8,8,8,7 bits msb->lsb).
    const int      SH[4] = {23, 15, 7, 0};
    const unsigned BM[4] = {255u, 255u, 255u, 127u};
#pragma unroll 1
    for (int r = 0; r < 4; ++r) {
        if (threadIdx.x < 256u) hist[threadIdx.x] = 0u;
        __syncthreads();
        int      sh     = SH[r];
        int      hish   = sh + (r == 3 ? 7 : 8);
        unsigned prefix = s_prefix;
        for (unsigned i = threadIdx.x; i < dom; i += 512u) {
            unsigned key, idx;
            fetch(i, key, idx);
            if (((key ^ prefix) >> hish) == 0u)
                atomicAdd(&hist[(key >> sh) & BM[r]], 1u);
        }
        __syncthreads();
        if (threadIdx.x == 0) {
            unsigned need = s_rem, acc = 0u;
            int bin = (int)BM[r];
            for (; bin > 0; --bin) {
                unsigned c = hist[bin];
                if (acc + c >= need) break;
                acc += c;
            }
            s_rem    = need - acc;
            s_prefix = prefix | ((unsigned)bin << sh);
        }
        __syncthreads();
    }

    unsigned thr = s_prefix;
    unsigned req = s_rem;

    for (unsigned i = threadIdx.x; i < dom; i += 512u) {
        unsigned key, idx;
        fetch(i, key, idx);
        if (key > thr) {
            out[gbase + idx] += 1.0f;
        } else if (key == thr) {
            unsigned p = atomicAdd(&s_tcnt, 1u);
            if (p < (unsigned)MAXTIES) s_tidx[p] = idx;
        }
    }
    __syncthreads();

    unsigned tc = s_tcnt;
    if (tc <= (unsigned)MAXTIES) {
        // Tie-break like jax top_k: smallest original indices win.
        for (unsigned t = threadIdx.x; t < tc; t += 512u) {
            unsigned my = s_tidx[t], rank = 0u;
            for (unsigned j = 0; j < tc; ++j) rank += (s_tidx[j] < my) ? 1u : 0u;
            if (rank < req) out[gbase + my] += 1.0f;
        }
    } else {
        // Exact degenerate-ties fallback (unreachable on bench data).
        for (unsigned i = threadIdx.x; i < dom; i += 512u) {
            unsigned key, idx;
            fetch(i, key, idx);
            if (key != thr) continue;
            unsigned rank = 0u;
            for (unsigned j = 0; j < dom; ++j) {
                unsigned kj, ij;
                fetch(j, kj, ij);
                if (kj == thr && ij < idx) ++rank;
            }
            if (rank < req) out[gbase + idx] += 1.0f;
        }
    }
    __syncthreads();
    if (threadIdx.x == 0) { g_ocnt[b * 32] = 0; g_dcnt[b * 32] = 0; }
}

} // namespace

extern "C" void kernel_launch(void* const* d_in, const int* in_sizes, int n_in,
                              void* d_out, int out_size) {
    const float* diff = (const float*)d_in[0];
    const float* w    = (const float*)d_in[1];
    const int*   ep   = (const int*)d_in[2];
    float*       out  = (float*)d_out;

    k_main<<<B * BPB, 256>>>((const float4*)diff, (const float4*)w, (float4*)out);
    k_compact<<<B * CHUNKS, 256>>>();
    k_select<<<B, 512>>>(diff, out, ep);
}

// round 5
// speedup vs baseline: 10.1337x; 1.1063x over previous
#include <cuda_runtime.h>
#include <cstdint>
#include <cstddef>

// out[b] = weight[b] + top1000_scatter_mask(|difference[b]|), B=64, N=1M/batch.
// R5: interleaved block->batch mapping spreads per-batch counter atomics across
// the wave (~18 concurrent per counter), allowing direct dense gather in k_main.
// k_compact and all sparse/overflow buffers deleted.

namespace {

constexpr int B      = 64;
constexpr int NPB    = 1 << 20;       // elements per batch
constexpr int TOPN   = 1000;
constexpr unsigned CUT = 0x40200000u; // 2.5f abs-key cutoff (rank-1000 key ~3.29 sigma)
constexpr int BPB    = 1024;          // 1024-elem blocks per batch
constexpr int DCAP   = 32768;         // dense candidate capacity per batch (~2.6x mean)
constexpr int MAXTIES = 256;

__device__ unsigned g_dkey[B][DCAP];
__device__ unsigned g_didx[B][DCAP];
__device__ unsigned g_dcnt[B * 32];   // 128B-padded; reset by k_select each replay

// Streaming pass: out = weight; gather |diff| >= 2.5 directly into dense arrays.
// batch = blockIdx.x & 63  -> each wave spreads atomics across all 64 counters.
__global__ void __launch_bounds__(256) k_main(const float4* __restrict__ diff,
                                              const float4* __restrict__ w,
                                              float4* __restrict__ out) {
    __shared__ unsigned s_key[1024];
    __shared__ unsigned s_idx[1024];
    __shared__ unsigned s_n, s_base;
    if (threadIdx.x == 0) s_n = 0u;
    __syncthreads();

    unsigned b    = blockIdx.x & 63u;          // batch (interleaved mapping)
    unsigned bblk = blockIdx.x >> 6;           // block index within batch, 0..1023
    unsigned t    = (b << 18) + bblk * 256u + threadIdx.x;  // float4 index
    float4 d = __ldcs(&diff[t]);
    __stcs(&out[t], __ldcs(&w[t]));

    unsigned e0 = (bblk * 256u + threadIdx.x) << 2;  // element index within batch

    unsigned keys[4] = {__float_as_uint(d.x) & 0x7FFFFFFFu,
                        __float_as_uint(d.y) & 0x7FFFFFFFu,
                        __float_as_uint(d.z) & 0x7FFFFFFFu,
                        __float_as_uint(d.w) & 0x7FFFFFFFu};
#pragma unroll
    for (int j = 0; j < 4; ++j) {
        if (keys[j] >= CUT) {                  // ~1.24% of elements
            unsigned p = atomicAdd(&s_n, 1u);  // shared atomic, ~13/block
            s_key[p] = keys[j];                // p < 1024 by construction
            s_idx[p] = e0 + j;
        }
    }
    __syncthreads();

    unsigned n = s_n;
    if (n) {
        if (threadIdx.x == 0)
            s_base = atomicAdd(&g_dcnt[b * 32], n);  // 1 global atomic per block
        __syncthreads();
        unsigned base = s_base;
        for (unsigned i = threadIdx.x; i < n; i += 256u) {
            unsigned slot = base + i;
            if (slot < (unsigned)DCAP) {
                g_dkey[b][slot] = s_key[i];
                g_didx[b][slot] = s_idx[i];
            }
        }
    }
}

// Per-batch exact radix-select + scatter over the dense domain. One block/batch.
__global__ void __launch_bounds__(512) k_select(const float* __restrict__ diff,
                                                float* __restrict__ out,
                                                const int* __restrict__ ep) {
    int b = blockIdx.x;
    int epoch = ep[0];
    bool hot = (epoch > 1000) && (epoch < 18000) && (epoch % 200 == 0);
    if (!hot) { if (threadIdx.x == 0) g_dcnt[b * 32] = 0; return; }

    __shared__ unsigned hist[256];
    __shared__ unsigned s_prefix, s_rem, s_tcnt;
    __shared__ unsigned s_tidx[MAXTIES];

    unsigned raw  = g_dcnt[b * 32];
    // Fast path valid iff no candidate was dropped AND candidates cover top-1000.
    bool fast = (raw >= (unsigned)TOPN) && (raw <= (unsigned)DCAP);
    size_t gbase = (size_t)b * (size_t)NPB;
    unsigned dom = fast ? raw : (unsigned)NPB;

    if (threadIdx.x == 0) { s_prefix = 0u; s_rem = (unsigned)TOPN; s_tcnt = 0u; }
    __syncthreads();

    // 4-round radix select over 31-bit abs keys (8,8,8,7 bits msb->lsb).
    const int      SH[4] = {23, 15, 7, 0};
    const unsigned BM[4] = {255u, 255u, 255u, 127u};
#pragma unroll 1
    for (int r = 0; r < 4; ++r) {
        if (threadIdx.x < 256u) hist[threadIdx.x] = 0u;
        __syncthreads();
        int      sh     = SH[r];
        int      hish   = sh + (r == 3 ? 7 : 8);
        unsigned prefix = s_prefix;
        for (unsigned i = threadIdx.x; i < dom; i += 512u) {
            unsigned key = fast ? g_dkey[b][i]
                                : (__float_as_uint(diff[gbase + i]) & 0x7FFFFFFFu);
            if (((key ^ prefix) >> hish) == 0u)
                atomicAdd(&hist[(key >> sh) & BM[r]], 1u);
        }
        __syncthreads();
        if (threadIdx.x == 0) {
            unsigned need = s_rem, acc = 0u;
            int bin = (int)BM[r];
            for (; bin > 0; --bin) {
                unsigned c = hist[bin];
                if (acc + c >= need) break;
                acc += c;
            }
            s_rem    = need - acc;
            s_prefix = prefix | ((unsigned)bin << sh);
        }
        __syncthreads();
    }

    unsigned thr = s_prefix;   // exact rank-1000 key
    unsigned req = s_rem;      // how many == thr to include

    // Scatter strict winners; collect ties.
    for (unsigned i = threadIdx.x; i < dom; i += 512u) {
        unsigned key, idx;
        if (fast) { key = g_dkey[b][i]; idx = g_didx[b][i]; }
        else      { key = __float_as_uint(diff[gbase + i]) & 0x7FFFFFFFu; idx = i; }
        if (key > thr) {
            out[gbase + idx] += 1.0f;
        } else if (key == thr) {
            unsigned p = atomicAdd(&s_tcnt, 1u);
            if (p < (unsigned)MAXTIES) s_tidx[p] = idx;
        }
    }
    __syncthreads();

    unsigned tc = s_tcnt;
    if (tc <= (unsigned)MAXTIES) {
        // Tie-break like jax top_k: smallest original indices win.
        for (unsigned t = threadIdx.x; t < tc; t += 512u) {
            unsigned my = s_tidx[t], rank = 0u;
            for (unsigned j = 0; j < tc; ++j) rank += (s_tidx[j] < my) ? 1u : 0u;
            if (rank < req) out[gbase + my] += 1.0f;
        }
    } else {
        // Exact degenerate-ties fallback (unreachable on bench data).
        for (unsigned i = threadIdx.x; i < dom; i += 512u) {
            unsigned key, idx;
            if (fast) { key = g_dkey[b][i]; idx = g_didx[b][i]; }
            else      { key = __float_as_uint(diff[gbase + i]) & 0x7FFFFFFFu; idx = i; }
            if (key != thr) continue;
            unsigned rank = 0u;
            for (unsigned j = 0; j < dom; ++j) {
                unsigned kj, ij;
                if (fast) { kj = g_dkey[b][j]; ij = g_didx[b][j]; }
                else      { kj = __float_as_uint(diff[gbase + j]) & 0x7FFFFFFFu; ij = j; }
                if (kj == thr && ij < idx) ++rank;
            }
            if (rank < req) out[gbase + idx] += 1.0f;
        }
    }
    __syncthreads();
    if (threadIdx.x == 0) g_dcnt[b * 32] = 0;   // reset for next graph replay
}

} // namespace

extern "C" void kernel_launch(void* const* d_in, const int* in_sizes, int n_in,
                              void* d_out, int out_size) {
    const float* diff = (const float*)d_in[0];
    const float* w    = (const float*)d_in[1];
    const int*   ep   = (const int*)d_in[2];
    float*       out  = (float*)d_out;

    k_main<<<B * BPB, 256>>>((const float4*)diff, (const float4*)w, (float4*)out);
    k_select<<<B, 512>>>(diff, out, ep);
}

// round 6
// speedup vs baseline: 10.3261x; 1.0190x over previous
#include <cuda_runtime.h>
#include <cstdint>
#include <cstddef>

// out[b] = weight[b] + top1000_scatter_mask(|difference[b]|), B=64, N=1M/batch.
// R6: k_select caches the whole candidate set in dynamic shared memory (one
// coalesced global pass), then runs all 4 radix rounds + scatter out of SMEM.
// (R5 post-mortem: k_select was 5 latency-bound global passes, 59.6us.)

namespace {

constexpr int B      = 64;
constexpr int NPB    = 1 << 20;       // elements per batch
constexpr int TOPN   = 1000;
constexpr unsigned CUT = 0x40200000u; // 2.5f abs-key cutoff (rank-1000 ~3.29 sigma)
constexpr int BPB    = 1024;          // 1024-elem blocks per batch in k_main
constexpr int DCAP   = 32768;         // dense capacity per batch
constexpr int CACHE  = 16384;         // smem cache entries (mean 12.4K, +36 sigma)
constexpr int MAXTIES = 256;

__device__ unsigned g_dkey[B][DCAP];
__device__ unsigned g_didx[B][DCAP];
__device__ unsigned g_dcnt[B * 32];   // 128B-padded; reset by k_select each replay

// Streaming pass: out = weight; gather |diff| >= 2.5 into dense per-batch arrays.
// batch = blockIdx.x & 63 spreads counter atomics across the wave.
__global__ void __launch_bounds__(256) k_main(const float4* __restrict__ diff,
                                              const float4* __restrict__ w,
                                              float4* __restrict__ out) {
    __shared__ unsigned s_key[1024];
    __shared__ unsigned s_idx[1024];
    __shared__ unsigned s_n, s_base;
    if (threadIdx.x == 0) s_n = 0u;
    __syncthreads();

    unsigned b    = blockIdx.x & 63u;
    unsigned bblk = blockIdx.x >> 6;
    unsigned t    = (b << 18) + bblk * 256u + threadIdx.x;
    float4 d = __ldcs(&diff[t]);
    __stcs(&out[t], __ldcs(&w[t]));

    unsigned e0 = (bblk * 256u + threadIdx.x) << 2;

    unsigned keys[4] = {__float_as_uint(d.x) & 0x7FFFFFFFu,
                        __float_as_uint(d.y) & 0x7FFFFFFFu,
                        __float_as_uint(d.z) & 0x7FFFFFFFu,
                        __float_as_uint(d.w) & 0x7FFFFFFFu};
#pragma unroll
    for (int j = 0; j < 4; ++j) {
        if (keys[j] >= CUT) {                 // ~1.24% of elements
            unsigned p = atomicAdd(&s_n, 1u);
            s_key[p] = keys[j];
            s_idx[p] = e0 + j;
        }
    }
    __syncthreads();

    unsigned n = s_n;
    if (n) {
        if (threadIdx.x == 0)
            s_base = atomicAdd(&g_dcnt[b * 32], n);
        __syncthreads();
        unsigned base = s_base;
        for (unsigned i = threadIdx.x; i < n; i += 256u) {
            unsigned slot = base + i;
            if (slot < (unsigned)DCAP) {
                g_dkey[b][slot] = s_key[i];
                g_didx[b][slot] = s_idx[i];
            }
        }
    }
}

// Per-batch exact radix-select + scatter. One block/batch; candidates in SMEM.
__global__ void __launch_bounds__(512) k_select(const float* __restrict__ diff,
                                                float* __restrict__ out,
                                                const int* __restrict__ ep) {
    extern __shared__ unsigned sm[];           // [CACHE] keys | [CACHE] idx
    unsigned* sk = sm;
    unsigned* si = sm + CACHE;

    int b = blockIdx.x;
    int epoch = ep[0];
    bool hot = (epoch > 1000) && (epoch < 18000) && (epoch % 200 == 0);
    if (!hot) { if (threadIdx.x == 0) g_dcnt[b * 32] = 0; return; }

    __shared__ unsigned hist[256];
    __shared__ unsigned s_prefix, s_rem, s_tcnt;
    __shared__ unsigned s_tidx[MAXTIES];

    unsigned raw = g_dcnt[b * 32];
    bool fast = (raw >= (unsigned)TOPN) && (raw <= (unsigned)DCAP);
    bool sfit = fast && (raw <= (unsigned)CACHE);   // smem-cached path
    size_t gbase = (size_t)b * (size_t)NPB;
    unsigned dom = fast ? raw : (unsigned)NPB;

    if (threadIdx.x == 0) { s_prefix = 0u; s_rem = (unsigned)TOPN; s_tcnt = 0u; }

    if (sfit) {
        // One coalesced global pass: stage candidates in shared memory.
        for (unsigned i = threadIdx.x; i < dom; i += 512u) {
            sk[i] = g_dkey[b][i];
            si[i] = g_didx[b][i];
        }
    }
    __syncthreads();

    auto getkey = [&](unsigned i) -> unsigned {
        if (sfit) return sk[i];
        if (fast) return g_dkey[b][i];
        return __float_as_uint(diff[gbase + i]) & 0x7FFFFFFFu;
    };
    auto getidx = [&](unsigned i) -> unsigned {
        if (sfit) return si[i];
        if (fast) return g_didx[b][i];
        return i;
    };

    // 4-round radix select over 31-bit abs keys (8,8,8,7 bits msb->lsb).
    const int      SH[4] = {23, 15, 7, 0};
    const unsigned BM[4] = {255u, 255u, 255u, 127u};
#pragma unroll 1
    for (int r = 0; r < 4; ++r) {
        if (threadIdx.x < 256u) hist[threadIdx.x] = 0u;
        __syncthreads();
        int      sh     = SH[r];
        int      hish   = sh + (r == 3 ? 7 : 8);
        unsigned prefix = s_prefix;
        for (unsigned i = threadIdx.x; i < dom; i += 512u) {
            unsigned key = getkey(i);
            if (((key ^ prefix) >> hish) == 0u)
                atomicAdd(&hist[(key >> sh) & BM[r]], 1u);
        }
        __syncthreads();
        if (threadIdx.x == 0) {
            unsigned need = s_rem, acc = 0u;
            int bin = (int)BM[r];
            for (; bin > 0; --bin) {
                unsigned c = hist[bin];
                if (acc + c >= need) break;
                acc += c;
            }
            s_rem    = need - acc;
            s_prefix = prefix | ((unsigned)bin << sh);
        }
        __syncthreads();
    }

    unsigned thr = s_prefix;   // exact rank-1000 key
    unsigned req = s_rem;      // how many == thr to include

    // Scatter strict winners; collect ties.
    for (unsigned i = threadIdx.x; i < dom; i += 512u) {
        unsigned key = getkey(i);
        if (key > thr) {
            out[gbase + getidx(i)] += 1.0f;
        } else if (key == thr) {
            unsigned p = atomicAdd(&s_tcnt, 1u);
            if (p < (unsigned)MAXTIES) s_tidx[p] = getidx(i);
        }
    }
    __syncthreads();

    unsigned tc = s_tcnt;
    if (tc <= (unsigned)MAXTIES) {
        // Tie-break like jax top_k: smallest original indices win.
        for (unsigned t = threadIdx.x; t < tc; t += 512u) {
            unsigned my = s_tidx[t], rank = 0u;
            for (unsigned j = 0; j < tc; ++j) rank += (s_tidx[j] < my) ? 1u : 0u;
            if (rank < req) out[gbase + my] += 1.0f;
        }
    } else {
        // Exact degenerate-ties fallback (unreachable on bench data).
        for (unsigned i = threadIdx.x; i < dom; i += 512u) {
            unsigned key = getkey(i);
            if (key != thr) continue;
            unsigned idx = getidx(i), rank = 0u;
            for (unsigned j = 0; j < dom; ++j) {
                if (getkey(j) == thr && getidx(j) < idx) ++rank;
            }
            if (rank < req) out[gbase + idx] += 1.0f;
        }
    }
    __syncthreads();
    if (threadIdx.x == 0) g_dcnt[b * 32] = 0;   // reset for next graph replay
}

} // namespace

extern "C" void kernel_launch(void* const* d_in, const int* in_sizes, int n_in,
                              void* d_out, int out_size) {
    const float* diff = (const float*)d_in[0];
    const float* w    = (const float*)d_in[1];
    const int*   ep   = (const int*)d_in[2];
    float*       out  = (float*)d_out;

    static bool attr_set = false;
    if (!attr_set) {
        cudaFuncSetAttribute(k_select, cudaFuncAttributeMaxDynamicSharedMemorySize,
                             CACHE * 2 * (int)sizeof(unsigned));
        attr_set = true;
    }

    k_main<<<B * BPB, 256>>>((const float4*)diff, (const float4*)w, (float4*)out);
    k_select<<<B, 512, CACHE * 2 * sizeof(unsigned)>>>(diff, out, ep);
}

// round 7
// speedup vs baseline: 10.7197x; 1.0381x over previous
#include <cuda_runtime.h>
#include <cstdint>
#include <cstddef>

// out[b] = weight[b] + top1000_scatter_mask(|difference[b]|), B=64, N=1M/batch.
// R7: k_select = single 12-bit histogram + parallel suffix-scan + exact
// boundary ranking (replaces 4 radix rounds + serial thread-0 bin scan).

namespace {

constexpr int B      = 64;
constexpr int NPB    = 1 << 20;
constexpr int TOPN   = 1000;
constexpr unsigned CUT = 0x40200000u; // 2.5f abs-key cutoff
constexpr int BPB    = 1024;
constexpr int DCAP   = 32768;         // dense candidate capacity per batch
constexpr int CACHE  = 16384;         // smem cache entries
constexpr int NBIN   = 4096;          // 12-bit histogram (key>>19)
constexpr int BCAP   = 2048;          // boundary-bin list capacity (mean ~430)
constexpr int MAXTIES = 256;
constexpr int STH    = 1024;          // k_select threads

__device__ unsigned g_dkey[B][DCAP];
__device__ unsigned g_didx[B][DCAP];
__device__ unsigned g_dcnt[B * 32];   // 128B-padded; reset by k_select each replay

// Streaming pass: out = weight; gather |diff| >= 2.5 into dense per-batch arrays.
__global__ void __launch_bounds__(256) k_main(const float4* __restrict__ diff,
                                              const float4* __restrict__ w,
                                              float4* __restrict__ out) {
    __shared__ unsigned s_key[1024];
    __shared__ unsigned s_idx[1024];
    __shared__ unsigned s_n, s_base;
    if (threadIdx.x == 0) s_n = 0u;
    __syncthreads();

    unsigned b    = blockIdx.x & 63u;          // interleaved batch mapping
    unsigned bblk = blockIdx.x >> 6;
    unsigned t    = (b << 18) + bblk * 256u + threadIdx.x;
    float4 d = __ldcs(&diff[t]);
    __stcs(&out[t], __ldcs(&w[t]));

    unsigned e0 = (bblk * 256u + threadIdx.x) << 2;

    unsigned keys[4] = {__float_as_uint(d.x) & 0x7FFFFFFFu,
                        __float_as_uint(d.y) & 0x7FFFFFFFu,
                        __float_as_uint(d.z) & 0x7FFFFFFFu,
                        __float_as_uint(d.w) & 0x7FFFFFFFu};
#pragma unroll
    for (int j = 0; j < 4; ++j) {
        if (keys[j] >= CUT) {
            unsigned p = atomicAdd(&s_n, 1u);
            s_key[p] = keys[j];
            s_idx[p] = e0 + j;
        }
    }
    __syncthreads();

    unsigned n = s_n;
    if (n) {
        if (threadIdx.x == 0)
            s_base = atomicAdd(&g_dcnt[b * 32], n);
        __syncthreads();
        unsigned base = s_base;
        for (unsigned i = threadIdx.x; i < n; i += 256u) {
            unsigned slot = base + i;
            if (slot < (unsigned)DCAP) {
                g_dkey[b][slot] = s_key[i];
                g_didx[b][slot] = s_idx[i];
            }
        }
    }
}

__global__ void __launch_bounds__(STH) k_select(const float* __restrict__ diff,
                                                float* __restrict__ out,
                                                const int* __restrict__ ep) {
    extern __shared__ unsigned sm[];           // [CACHE] keys | [CACHE] idx
    unsigned* sk = sm;
    unsigned* si = sm + CACHE;

    __shared__ unsigned hist[NBIN];
    __shared__ unsigned s_scan[STH];
    __shared__ unsigned s_bkey[BCAP];
    __shared__ unsigned s_bidx[BCAP];
    __shared__ unsigned s_bn, s_p0, s_rem;
    __shared__ unsigned s_prefix, s_rem2, s_tcnt;
    __shared__ unsigned s_tidx[MAXTIES];

    int b = blockIdx.x;
    unsigned tid = threadIdx.x;
    int epoch = ep[0];
    bool hot = (epoch > 1000) && (epoch < 18000) && (epoch % 200 == 0);
    if (!hot) { if (tid == 0) g_dcnt[b * 32] = 0; return; }

    unsigned raw = g_dcnt[b * 32];
    bool fast = (raw >= (unsigned)TOPN) && (raw <= (unsigned)DCAP);
    bool sfit = fast && (raw <= (unsigned)CACHE);
    size_t gbase = (size_t)b * (size_t)NPB;
    unsigned dom = fast ? raw : (unsigned)NPB;

    bool done = false;

    if (sfit) {
        // ---------- Pass A: stage candidates + 12-bit histogram ----------
        for (unsigned i = tid; i < (unsigned)NBIN; i += STH) hist[i] = 0u;
        if (tid == 0) s_bn = 0u;
        __syncthreads();
        for (unsigned i = tid; i < dom; i += STH) {
            unsigned k = g_dkey[b][i];
            sk[i] = k;
            si[i] = g_didx[b][i];
            atomicAdd(&hist[k >> 19], 1u);
        }
        __syncthreads();

        // ---------- Parallel suffix scan over 4096 bins ----------
        // Thread t owns bins [4t, 4t+4). P = chunk sum; S = inclusive suffix sum.
        unsigned h0 = hist[tid * 4 + 0], h1 = hist[tid * 4 + 1];
        unsigned h2 = hist[tid * 4 + 2], h3 = hist[tid * 4 + 3];
        unsigned P = h0 + h1 + h2 + h3;
        s_scan[tid] = P;
        __syncthreads();
#pragma unroll
        for (unsigned off = 1; off < STH; off <<= 1) {
            unsigned v = (tid + off < STH) ? s_scan[tid + off] : 0u;
            __syncthreads();
            s_scan[tid] += v;
            __syncthreads();
        }
        // cumulative count of keys in bins strictly above this chunk
        unsigned above = s_scan[tid] - P;
        // descend within chunk from the top bin
        unsigned acc = above;
        unsigned hh[4] = {h3, h2, h1, h0};
#pragma unroll
        for (int q = 0; q < 4; ++q) {
            unsigned bin = tid * 4u + (3u - q);
            if (acc < (unsigned)TOPN && acc + hh[q] >= (unsigned)TOPN) {
                s_p0 = bin; s_rem = (unsigned)TOPN - acc;
            }
            acc += hh[q];
        }
        __syncthreads();

        unsigned p0  = s_p0;
        unsigned rem = s_rem;
        unsigned m   = hist[p0];

        if (m <= (unsigned)BCAP) {
            // ---------- Pass B: scatter strict winners, collect boundary ----
            for (unsigned i = tid; i < dom; i += STH) {
                unsigned k  = sk[i];
                unsigned bi = k >> 19;
                if (bi > p0) {
                    out[gbase + si[i]] += 1.0f;
                } else if (bi == p0) {
                    unsigned p = atomicAdd(&s_bn, 1u);
                    s_bkey[p] = k;          // p < m <= BCAP guaranteed
                    s_bidx[p] = si[i];
                }
            }
            __syncthreads();

            // ---------- Exact boundary ranking (key desc, idx asc) ----------
            for (unsigned t = tid; t < m; t += STH) {
                unsigned mk = s_bkey[t], mi = s_bidx[t];
                unsigned rank = 0u;
                for (unsigned j = 0; j < m; ++j) {
                    unsigned kj = s_bkey[j];
                    rank += (kj > mk || (kj == mk && s_bidx[j] < mi)) ? 1u : 0u;
                }
                if (rank < rem) out[gbase + mi] += 1.0f;
            }
            done = true;
        }
        __syncthreads();
    }

    if (!done) {
        // ======= Fallback: exact 4-round radix select (never taken on bench) ====
        if (tid == 0) { s_prefix = 0u; s_rem2 = (unsigned)TOPN; s_tcnt = 0u; }
        __syncthreads();

        auto getkey = [&](unsigned i) -> unsigned {
            if (sfit) return sk[i];
            if (fast) return g_dkey[b][i];
            return __float_as_uint(diff[gbase + i]) & 0x7FFFFFFFu;
        };
        auto getidx = [&](unsigned i) -> unsigned {
            if (sfit) return si[i];
            if (fast) return g_didx[b][i];
            return i;
        };

        const int      SH[4] = {23, 15, 7, 0};
        const unsigned BM[4] = {255u, 255u, 255u, 127u};
#pragma unroll 1
        for (int r = 0; r < 4; ++r) {
            if (tid < 256u) hist[tid] = 0u;
            __syncthreads();
            int      sh     = SH[r];
            int      hish   = sh + (r == 3 ? 7 : 8);
            unsigned prefix = s_prefix;
            for (unsigned i = tid; i < dom; i += STH) {
                unsigned key = getkey(i);
                if (((key ^ prefix) >> hish) == 0u)
                    atomicAdd(&hist[(key >> sh) & BM[r]], 1u);
            }
            __syncthreads();
            if (tid == 0) {
                unsigned need = s_rem2, acc = 0u;
                int bin = (int)BM[r];
                for (; bin > 0; --bin) {
                    unsigned c = hist[bin];
                    if (acc + c >= need) break;
                    acc += c;
                }
                s_rem2   = need - acc;
                s_prefix = prefix | ((unsigned)bin << sh);
            }
            __syncthreads();
        }

        unsigned thr = s_prefix;
        unsigned req = s_rem2;

        for (unsigned i = tid; i < dom; i += STH) {
            unsigned key = getkey(i);
            if (key > thr) {
                out[gbase + getidx(i)] += 1.0f;
            } else if (key == thr) {
                unsigned p = atomicAdd(&s_tcnt, 1u);
                if (p < (unsigned)MAXTIES) s_tidx[p] = getidx(i);
            }
        }
        __syncthreads();

        unsigned tc = s_tcnt;
        if (tc <= (unsigned)MAXTIES) {
            for (unsigned t = tid; t < tc; t += STH) {
                unsigned my = s_tidx[t], rank = 0u;
                for (unsigned j = 0; j < tc; ++j) rank += (s_tidx[j] < my) ? 1u : 0u;
                if (rank < req) out[gbase + my] += 1.0f;
            }
        } else {
            for (unsigned i = tid; i < dom; i += STH) {
                unsigned key = getkey(i);
                if (key != thr) continue;
                unsigned idx = getidx(i), rank = 0u;
                for (unsigned j = 0; j < dom; ++j) {
                    if (getkey(j) == thr && getidx(j) < idx) ++rank;
                }
                if (rank < req) out[gbase + idx] += 1.0f;
            }
        }
        __syncthreads();
    }

    if (tid == 0) g_dcnt[b * 32] = 0;   // reset for next graph replay
}

} // namespace

extern "C" void kernel_launch(void* const* d_in, const int* in_sizes, int n_in,
                              void* d_out, int out_size) {
    const float* diff = (const float*)d_in[0];
    const float* w    = (const float*)d_in[1];
    const int*   ep   = (const int*)d_in[2];
    float*       out  = (float*)d_out;

    static bool attr_set = false;
    if (!attr_set) {
        cudaFuncSetAttribute(k_select, cudaFuncAttributeMaxDynamicSharedMemorySize,
                             CACHE * 2 * (int)sizeof(unsigned));
        attr_set = true;
    }

    k_main<<<B * BPB, 256>>>((const float4*)diff, (const float4*)w, (float4*)out);
    k_select<<<B, STH, CACHE * 2 * sizeof(unsigned)>>>(diff, out, ep);
}

// round 8
// speedup vs baseline: 12.1519x; 1.1336x over previous
#include <cuda_runtime.h>
#include <cstdint>
#include <cstddef>

// out[b] = weight[b] + top1000_scatter_mask(|difference[b]|), B=64, N=1M/batch.
// R8: histogram built for free inside k_main (spread global atomics, hidden
// under the HBM stream); k_select = hist load + parallel suffix scan + ONE
// candidate pass. Fine bins ((key-CUT)>>12) make the boundary bin ~7 elements.

namespace {

constexpr int B      = 64;
constexpr int NPB    = 1 << 20;
constexpr int TOPN   = 1000;
constexpr unsigned CUT = 0x40200000u; // 2.5f abs-key cutoff (rank-1000 ~3.29 sigma)
constexpr int BPB    = 1024;
constexpr int DCAP   = 32768;         // dense candidate capacity per batch
constexpr int NBIN   = 4096;          // fine bins: (key - CUT) >> 12, clamped
constexpr int BCAP   = 1024;          // boundary-bin capacity (mean ~7)
constexpr int MAXTIES = 256;
constexpr int STH    = 1024;

__device__ unsigned g_dkey[B][DCAP];
__device__ unsigned g_didx[B][DCAP];
__device__ unsigned g_dcnt[B * 32];   // 128B-padded; reset by k_select each replay
__device__ unsigned g_hist[B][NBIN];  // built by k_main; zeroed by k_select

__device__ __forceinline__ unsigned keybin(unsigned key) {
    unsigned d = key - CUT;           // key >= CUT on candidate path
    unsigned bi = d >> 12;
    return bi < (unsigned)NBIN ? bi : (unsigned)(NBIN - 1);
}

// Streaming pass: out = weight; gather |diff| >= 2.5 + per-batch fine histogram.
__global__ void __launch_bounds__(256) k_main(const float4* __restrict__ diff,
                                              const float4* __restrict__ w,
                                              float4* __restrict__ out) {
    __shared__ unsigned s_key[1024];
    __shared__ unsigned s_idx[1024];
    __shared__ unsigned s_n, s_base;
    if (threadIdx.x == 0) s_n = 0u;
    __syncthreads();

    unsigned b    = blockIdx.x & 63u;          // interleaved batch mapping
    unsigned bblk = blockIdx.x >> 6;
    unsigned t    = (b << 18) + bblk * 256u + threadIdx.x;
    float4 d = __ldcs(&diff[t]);
    __stcs(&out[t], __ldcs(&w[t]));

    unsigned e0 = (bblk * 256u + threadIdx.x) << 2;

    unsigned keys[4] = {__float_as_uint(d.x) & 0x7FFFFFFFu,
                        __float_as_uint(d.y) & 0x7FFFFFFFu,
                        __float_as_uint(d.z) & 0x7FFFFFFFu,
                        __float_as_uint(d.w) & 0x7FFFFFFFu};
#pragma unroll
    for (int j = 0; j < 4; ++j) {
        if (keys[j] >= CUT) {                 // ~1.24% of elements
            unsigned p = atomicAdd(&s_n, 1u);
            s_key[p] = keys[j];
            s_idx[p] = e0 + j;
        }
    }
    __syncthreads();

    unsigned n = s_n;
    if (n) {
        if (threadIdx.x == 0)
            s_base = atomicAdd(&g_dcnt[b * 32], n);
        __syncthreads();
        unsigned base = s_base;
        for (unsigned i = threadIdx.x; i < n; i += 256u) {
            unsigned k = s_key[i];
            unsigned slot = base + i;
            if (slot < (unsigned)DCAP) {
                g_dkey[b][slot] = k;
                g_didx[b][slot] = s_idx[i];
            }
            atomicAdd(&g_hist[b][keybin(k)], 1u);  // ~13/block, spread bins: hidden
        }
    }
}

// Per-batch selection: hist scan + one candidate pass. One block per batch.
__global__ void __launch_bounds__(STH) k_select(const float* __restrict__ diff,
                                                float* __restrict__ out,
                                                const int* __restrict__ ep) {
    __shared__ unsigned hist[NBIN];
    __shared__ unsigned s_scan[STH];
    __shared__ unsigned s_bkey[BCAP];
    __shared__ unsigned s_bidx[BCAP];
    __shared__ unsigned s_bn, s_p0, s_rem;
    __shared__ unsigned s_prefix, s_rem2, s_tcnt;
    __shared__ unsigned s_tidx[MAXTIES];

    int b = blockIdx.x;
    unsigned tid = threadIdx.x;
    int epoch = ep[0];
    bool hot = (epoch > 1000) && (epoch < 18000) && (epoch % 200 == 0);

    unsigned raw = g_dcnt[b * 32];
    bool fast = (raw >= (unsigned)TOPN) && (raw <= (unsigned)DCAP);
    size_t gbase = (size_t)b * (size_t)NPB;
    unsigned dom = fast ? raw : (unsigned)NPB;

    bool done = !hot;

    if (hot && fast) {
        // ---- Load per-batch histogram (coalesced) ----
        unsigned h0 = g_hist[b][tid * 4 + 0], h1 = g_hist[b][tid * 4 + 1];
        unsigned h2 = g_hist[b][tid * 4 + 2], h3 = g_hist[b][tid * 4 + 3];
        hist[tid * 4 + 0] = h0; hist[tid * 4 + 1] = h1;
        hist[tid * 4 + 2] = h2; hist[tid * 4 + 3] = h3;
        if (tid == 0) s_bn = 0u;

        // ---- Parallel inclusive suffix scan over 1024 chunk sums ----
        unsigned P = h0 + h1 + h2 + h3;
        s_scan[tid] = P;
        __syncthreads();
#pragma unroll
        for (unsigned off = 1; off < STH; off <<= 1) {
            unsigned v = (tid + off < STH) ? s_scan[tid + off] : 0u;
            __syncthreads();
            s_scan[tid] += v;
            __syncthreads();
        }
        unsigned above = s_scan[tid] - P;   // keys in bins strictly above chunk
        unsigned acc = above;
        unsigned hh[4] = {h3, h2, h1, h0};
#pragma unroll
        for (int q = 0; q < 4; ++q) {
            unsigned bin = tid * 4u + (3u - q);
            if (acc < (unsigned)TOPN && acc + hh[q] >= (unsigned)TOPN) {
                s_p0 = bin; s_rem = (unsigned)TOPN - acc;
            }
            acc += hh[q];
        }
        __syncthreads();

        unsigned p0  = s_p0;
        unsigned rem = s_rem;
        unsigned m   = hist[p0];

        if (m <= (unsigned)BCAP) {
            // ---- Single pass: scatter winners, collect boundary bin ----
            for (unsigned i = tid; i < dom; i += STH) {
                unsigned k  = g_dkey[b][i];
                unsigned bi = keybin(k);
                if (bi > p0) {
                    out[gbase + g_didx[b][i]] += 1.0f;
                } else if (bi == p0) {
                    unsigned p = atomicAdd(&s_bn, 1u);
                    s_bkey[p] = k;                     // p < m <= BCAP
                    s_bidx[p] = g_didx[b][i];
                }
            }
            __syncthreads();
            // ---- Exact boundary ranking (key desc, idx asc) ----
            for (unsigned t = tid; t < m; t += STH) {
                unsigned mk = s_bkey[t], mi = s_bidx[t];
                unsigned rank = 0u;
                for (unsigned j = 0; j < m; ++j) {
                    unsigned kj = s_bkey[j];
                    rank += (kj > mk || (kj == mk && s_bidx[j] < mi)) ? 1u : 0u;
                }
                if (rank < rem) out[gbase + mi] += 1.0f;
            }
            done = true;
        }
        __syncthreads();
    }

    if (!done) {
        // ==== Fallback: exact 4-round radix select (unreachable on bench) ====
        if (tid == 0) { s_prefix = 0u; s_rem2 = (unsigned)TOPN; s_tcnt = 0u; }
        __syncthreads();

        auto getkey = [&](unsigned i) -> unsigned {
            if (fast) return g_dkey[b][i];
            return __float_as_uint(diff[gbase + i]) & 0x7FFFFFFFu;
        };
        auto getidx = [&](unsigned i) -> unsigned {
            if (fast) return g_didx[b][i];
            return i;
        };

        const int      SH[4] = {23, 15, 7, 0};
        const unsigned BM[4] = {255u, 255u, 255u, 127u};
#pragma unroll 1
        for (int r = 0; r < 4; ++r) {
            if (tid < 256u) hist[tid] = 0u;
            __syncthreads();
            int      sh     = SH[r];
            int      hish   = sh + (r == 3 ? 7 : 8);
            unsigned prefix = s_prefix;
            for (unsigned i = tid; i < dom; i += STH) {
                unsigned key = getkey(i);
                if (((key ^ prefix) >> hish) == 0u)
                    atomicAdd(&hist[(key >> sh) & BM[r]], 1u);
            }
            __syncthreads();
            if (tid == 0) {
                unsigned need = s_rem2, acc = 0u;
                int bin = (int)BM[r];
                for (; bin > 0; --bin) {
                    unsigned c = hist[bin];
                    if (acc + c >= need) break;
                    acc += c;
                }
                s_rem2   = need - acc;
                s_prefix = prefix | ((unsigned)bin << sh);
            }
            __syncthreads();
        }

        unsigned thr = s_prefix;
        unsigned req = s_rem2;

        for (unsigned i = tid; i < dom; i += STH) {
            unsigned key = getkey(i);
            if (key > thr) {
                out[gbase + getidx(i)] += 1.0f;
            } else if (key == thr) {
                unsigned p = atomicAdd(&s_tcnt, 1u);
                if (p < (unsigned)MAXTIES) s_tidx[p] = getidx(i);
            }
        }
        __syncthreads();

        unsigned tc = s_tcnt;
        if (tc <= (unsigned)MAXTIES) {
            for (unsigned t = tid; t < tc; t += STH) {
                unsigned my = s_tidx[t], rank = 0u;
                for (unsigned j = 0; j < tc; ++j) rank += (s_tidx[j] < my) ? 1u : 0u;
                if (rank < req) out[gbase + my] += 1.0f;
            }
        } else {
            for (unsigned i = tid; i < dom; i += STH) {
                unsigned key = getkey(i);
                if (key != thr) continue;
                unsigned idx = getidx(i), rank = 0u;
                for (unsigned j = 0; j < dom; ++j) {
                    if (getkey(j) == thr && getidx(j) < idx) ++rank;
                }
                if (rank < req) out[gbase + idx] += 1.0f;
            }
        }
        __syncthreads();
    }

    // Epilogue (all paths): zero this batch's histogram + counter for next replay.
    for (unsigned i = tid; i < (unsigned)NBIN; i += STH) g_hist[b][i] = 0u;
    if (tid == 0) g_dcnt[b * 32] = 0u;
}

} // namespace

extern "C" void kernel_launch(void* const* d_in, const int* in_sizes, int n_in,
                              void* d_out, int out_size) {
    const float* diff = (const float*)d_in[0];
    const float* w    = (const float*)d_in[1];
    const int*   ep   = (const int*)d_in[2];
    float*       out  = (float*)d_out;

    k_main<<<B * BPB, 256>>>((const float4*)diff, (const float4*)w, (float4*)out);
    k_select<<<B, STH>>>(diff, out, ep);
}

// round 9
// speedup vs baseline: 13.6282x; 1.1215x over previous
#include <cuda_runtime.h>
#include <cstdint>
#include <cstddef>

// out[b] = weight[b] + top1000_scatter_mask(|difference[b]|), B=64, N=1M/batch.
// R9: CUT raised to 3.2 sigma (candidates ~1374/batch, 9x fewer) + warp-shuffle
// suffix scan (3 barriers instead of 20). Histogram still built free in k_main.

namespace {

constexpr int B      = 64;
constexpr int NPB    = 1 << 20;
constexpr int TOPN   = 1000;
constexpr unsigned CUT = 0x404CCCCDu; // float bits of 3.2f (rank-1000 ~3.29 sigma)
constexpr int BPB    = 1024;
constexpr int DCAP   = 16384;         // dense candidate capacity (mean ~1374)
constexpr int NBIN   = 4096;          // fine bins: (key - CUT) >> 12, clamped
constexpr int BCAP   = 1024;          // boundary-bin capacity (mean ~7)
constexpr int MAXTIES = 256;
constexpr int STH    = 1024;

__device__ unsigned g_dkey[B][DCAP];
__device__ unsigned g_didx[B][DCAP];
__device__ unsigned g_dcnt[B * 32];   // 128B-padded; reset by k_select each replay
__device__ unsigned g_hist[B][NBIN];  // built by k_main; zeroed by k_select

__device__ __forceinline__ unsigned keybin(unsigned key) {
    unsigned d = key - CUT;           // key >= CUT on candidate path
    unsigned bi = d >> 12;
    return bi < (unsigned)NBIN ? bi : (unsigned)(NBIN - 1);
}

// Streaming pass: out = weight; gather |diff| >= 3.2 + per-batch fine histogram.
__global__ void __launch_bounds__(256) k_main(const float4* __restrict__ diff,
                                              const float4* __restrict__ w,
                                              float4* __restrict__ out) {
    __shared__ unsigned s_key[1024];
    __shared__ unsigned s_idx[1024];
    __shared__ unsigned s_n, s_base;
    if (threadIdx.x == 0) s_n = 0u;
    __syncthreads();

    unsigned b    = blockIdx.x & 63u;          // interleaved batch mapping
    unsigned bblk = blockIdx.x >> 6;
    unsigned t    = (b << 18) + bblk * 256u + threadIdx.x;
    float4 d = __ldcs(&diff[t]);
    __stcs(&out[t], __ldcs(&w[t]));

    unsigned e0 = (bblk * 256u + threadIdx.x) << 2;

    unsigned keys[4] = {__float_as_uint(d.x) & 0x7FFFFFFFu,
                        __float_as_uint(d.y) & 0x7FFFFFFFu,
                        __float_as_uint(d.z) & 0x7FFFFFFFu,
                        __float_as_uint(d.w) & 0x7FFFFFFFu};
#pragma unroll
    for (int j = 0; j < 4; ++j) {
        if (keys[j] >= CUT) {                 // ~0.137% of elements
            unsigned p = atomicAdd(&s_n, 1u);
            s_key[p] = keys[j];
            s_idx[p] = e0 + j;
        }
    }
    __syncthreads();

    unsigned n = s_n;
    if (n) {
        if (threadIdx.x == 0)
            s_base = atomicAdd(&g_dcnt[b * 32], n);
        __syncthreads();
        unsigned base = s_base;
        for (unsigned i = threadIdx.x; i < n; i += 256u) {
            unsigned k = s_key[i];
            unsigned slot = base + i;
            if (slot < (unsigned)DCAP) {
                g_dkey[b][slot] = k;
                g_didx[b][slot] = s_idx[i];
            }
            atomicAdd(&g_hist[b][keybin(k)], 1u);  // ~1.4/block, spread: hidden
        }
    }
}

// Per-batch selection: hist scan + one short candidate pass. One block/batch.
__global__ void __launch_bounds__(STH) k_select(const float* __restrict__ diff,
                                                float* __restrict__ out,
                                                const int* __restrict__ ep) {
    __shared__ unsigned hist[NBIN];
    __shared__ unsigned s_wsum[32], s_wsuf[32];
    __shared__ unsigned s_bkey[BCAP];
    __shared__ unsigned s_bidx[BCAP];
    __shared__ unsigned s_bn, s_p0, s_rem;
    __shared__ unsigned s_prefix, s_rem2, s_tcnt;
    __shared__ unsigned s_tidx[MAXTIES];

    int b = blockIdx.x;
    unsigned tid  = threadIdx.x;
    unsigned lane = tid & 31u;
    unsigned wid  = tid >> 5;
    int epoch = ep[0];
    bool hot = (epoch > 1000) && (epoch < 18000) && (epoch % 200 == 0);

    unsigned raw = g_dcnt[b * 32];
    bool fast = (raw >= (unsigned)TOPN) && (raw <= (unsigned)DCAP);
    size_t gbase = (size_t)b * (size_t)NPB;
    unsigned dom = fast ? raw : (unsigned)NPB;

    bool done = !hot;

    if (hot && fast) {
        // ---- Load per-batch histogram (coalesced, 4 per thread) ----
        unsigned h0 = g_hist[b][tid * 4 + 0], h1 = g_hist[b][tid * 4 + 1];
        unsigned h2 = g_hist[b][tid * 4 + 2], h3 = g_hist[b][tid * 4 + 3];
        hist[tid * 4 + 0] = h0; hist[tid * 4 + 1] = h1;
        hist[tid * 4 + 2] = h2; hist[tid * 4 + 3] = h3;
        if (tid == 0) s_bn = 0u;

        // ---- Warp-shuffle inclusive suffix scan over 1024 chunk sums ----
        unsigned P = h0 + h1 + h2 + h3;
        unsigned s = P;
#pragma unroll
        for (unsigned off = 1; off < 32; off <<= 1) {
            unsigned v = __shfl_down_sync(0xFFFFFFFFu, s, off);
            if (lane + off < 32u) s += v;
        }
        if (lane == 0) s_wsum[wid] = s;      // whole-warp sum
        __syncthreads();
        if (wid == 0) {
            unsigned tsum = s_wsum[lane];
            unsigned ss = tsum;
#pragma unroll
            for (unsigned off = 1; off < 32; off <<= 1) {
                unsigned v = __shfl_down_sync(0xFFFFFFFFu, ss, off);
                if (lane + off < 32u) ss += v;
            }
            s_wsuf[lane] = ss - tsum;        // sum of warps strictly after
        }
        __syncthreads();
        unsigned suffix_incl = s + s_wsuf[wid];  // keys in chunks tid..1023
        unsigned above = suffix_incl - P;        // keys in bins strictly above chunk
        unsigned acc = above;
        unsigned hh[4] = {h3, h2, h1, h0};
#pragma unroll
        for (int q = 0; q < 4; ++q) {
            unsigned bin = tid * 4u + (3u - q);
            if (acc < (unsigned)TOPN && acc + hh[q] >= (unsigned)TOPN) {
                s_p0 = bin; s_rem = (unsigned)TOPN - acc;
            }
            acc += hh[q];
        }
        __syncthreads();

        unsigned p0  = s_p0;
        unsigned rem = s_rem;
        unsigned m   = hist[p0];

        if (m <= (unsigned)BCAP) {
            // ---- Single short pass: scatter winners, collect boundary bin ----
            for (unsigned i = tid; i < dom; i += STH) {
                unsigned k  = g_dkey[b][i];
                unsigned bi = keybin(k);
                if (bi > p0) {
                    out[gbase + g_didx[b][i]] += 1.0f;
                } else if (bi == p0) {
                    unsigned p = atomicAdd(&s_bn, 1u);
                    s_bkey[p] = k;                     // p < m <= BCAP
                    s_bidx[p] = g_didx[b][i];
                }
            }
            __syncthreads();
            // ---- Exact boundary ranking (key desc, idx asc) ----
            for (unsigned t = tid; t < m; t += STH) {
                unsigned mk = s_bkey[t], mi = s_bidx[t];
                unsigned rank = 0u;
                for (unsigned j = 0; j < m; ++j) {
                    unsigned kj = s_bkey[j];
                    rank += (kj > mk || (kj == mk && s_bidx[j] < mi)) ? 1u : 0u;
                }
                if (rank < rem) out[gbase + mi] += 1.0f;
            }
            done = true;
        }
        __syncthreads();
    }

    if (!done) {
        // ==== Fallback: exact 4-round radix select over full batch ====
        if (tid == 0) { s_prefix = 0u; s_rem2 = (unsigned)TOPN; s_tcnt = 0u; }
        __syncthreads();

        auto getkey = [&](unsigned i) -> unsigned {
            if (fast) return g_dkey[b][i];
            return __float_as_uint(diff[gbase + i]) & 0x7FFFFFFFu;
        };
        auto getidx = [&](unsigned i) -> unsigned {
            if (fast) return g_didx[b][i];
            return i;
        };

        const int      SH[4] = {23, 15, 7, 0};
        const unsigned BM[4] = {255u, 255u, 255u, 127u};
#pragma unroll 1
        for (int r = 0; r < 4; ++r) {
            if (tid < 256u) hist[tid] = 0u;
            __syncthreads();
            int      sh     = SH[r];
            int      hish   = sh + (r == 3 ? 7 : 8);
            unsigned prefix = s_prefix;
            for (unsigned i = tid; i < dom; i += STH) {
                unsigned key = getkey(i);
                if (((key ^ prefix) >> hish) == 0u)
                    atomicAdd(&hist[(key >> sh) & BM[r]], 1u);
            }
            __syncthreads();
            if (tid == 0) {
                unsigned need = s_rem2, acc = 0u;
                int bin = (int)BM[r];
                for (; bin > 0; --bin) {
                    unsigned c = hist[bin];
                    if (acc + c >= need) break;
                    acc += c;
                }
                s_rem2   = need - acc;
                s_prefix = prefix | ((unsigned)bin << sh);
            }
            __syncthreads();
        }

        unsigned thr = s_prefix;
        unsigned req = s_rem2;

        for (unsigned i = tid; i < dom; i += STH) {
            unsigned key = getkey(i);
            if (key > thr) {
                out[gbase + getidx(i)] += 1.0f;
            } else if (key == thr) {
                unsigned p = atomicAdd(&s_tcnt, 1u);
                if (p < (unsigned)MAXTIES) s_tidx[p] = getidx(i);
            }
        }
        __syncthreads();

        unsigned tc = s_tcnt;
        if (tc <= (unsigned)MAXTIES) {
            for (unsigned t = tid; t < tc; t += STH) {
                unsigned my = s_tidx[t], rank = 0u;
                for (unsigned j = 0; j < tc; ++j) rank += (s_tidx[j] < my) ? 1u : 0u;
                if (rank < req) out[gbase + my] += 1.0f;
            }
        } else {
            for (unsigned i = tid; i < dom; i += STH) {
                unsigned key = getkey(i);
                if (key != thr) continue;
                unsigned idx = getidx(i), rank = 0u;
                for (unsigned j = 0; j < dom; ++j) {
                    if (getkey(j) == thr && getidx(j) < idx) ++rank;
                }
                if (rank < req) out[gbase + idx] += 1.0f;
            }
        }
        __syncthreads();
    }

    // Epilogue (all paths): zero this batch's histogram + counter for next replay.
#pragma unroll
    for (int q = 0; q < 4; ++q) g_hist[b][tid * 4u + q] = 0u;
    if (tid == 0) g_dcnt[b * 32] = 0u;
}

} // namespace

extern "C" void kernel_launch(void* const* d_in, const int* in_sizes, int n_in,
                              void* d_out, int out_size) {
    const float* diff = (const float*)d_in[0];
    const float* w    = (const float*)d_in[1];
    const int*   ep   = (const int*)d_in[2];
    float*       out  = (float*)d_out;

    k_main<<<B * BPB, 256>>>((const float4*)diff, (const float4*)w, (float4*)out);
    k_select<<<B, STH>>>(diff, out, ep);
}